// round 8
// baseline (speedup 1.0000x reference)
#include <cuda_runtime.h>
#include <cstdint>

// Problem constants
static constexpr int B = 64, T = 512, D = 1024, S = 1024, U = 10;
static constexpr int CT   = 32;          // timesteps per block
static constexpr int NCHK = T / CT;      // 16 chunks per batch

// Scratch (device globals: no allocation allowed)
__device__ float g_cpart[B * NCHK * D];  // per-block context partials (4 MB)
__device__ float g_e[B * T];             // exp(e)

typedef unsigned long long ull;

// ---------- packed f32x2 helpers (sm_103a) ----------
static __device__ __forceinline__ ull pack2(float x, float y) {
    ull r; asm("mov.b64 %0, {%1, %2};" : "=l"(r) : "f"(x), "f"(y)); return r;
}
static __device__ __forceinline__ float2 unpack2(ull v) {
    float2 r; asm("mov.b64 {%0, %1}, %2;" : "=f"(r.x), "=f"(r.y) : "l"(v)); return r;
}
static __device__ __forceinline__ ull fma2(ull a, ull b, ull c) {
    ull d; asm("fma.rn.f32x2 %0, %1, %2, %3;" : "=l"(d) : "l"(a), "l"(b), "l"(c)); return d;
}
// accurate tanh via exp identity (~1e-6 rel)
static __device__ __forceinline__ float fast_tanh(float x) {
    float ex = __expf(2.0f * x);
    return 1.0f - __fdividef(2.0f, ex + 1.0f);
}
static __device__ __forceinline__ void pf_l2(const void* p) {
    asm volatile("prefetch.global.L2 [%0];" :: "l"(p));
}

// ---------- K1: fused u2 + e + max-free softmax numerator + context ----------
// grid (NCHK, B), 256 threads = 8 warps = 4 pairs. Pair owns 8 t (2 groups of 4);
// warps in a pair split d 512/512. One weight LDS.128 serves 4 packed timesteps.
__global__ void __launch_bounds__(256, 2)
k1_main(const float* __restrict__ a,  const float* __restrict__ sp,
        const float* __restrict__ W1, const float* __restrict__ W2v,
        const float* __restrict__ b1, const float* __restrict__ b2) {
    const int ch = blockIdx.x, b = blockIdx.y;
    const int tid = threadIdx.x, w = tid >> 5, lane = tid & 31;
    const int side = w & 1, pair = w >> 1;

    __shared__ float ws[U][D];            // W1 front, transposed (40 KB)
    __shared__ float red[8][U];
    __shared__ float u2s[U], w2s[U];
    __shared__ float b2s;
    __shared__ __align__(16) float pairbuf[2][4][2][40];  // [grp parity][pair][side][4t*10u]

    // ---- phase 0: transpose W1[:D] into smem; u2[b] inline ----
    {
        const int d0 = 4 * tid;
        float tmp[4][U];
#pragma unroll
        for (int j = 0; j < 4; j++) {
            const float2* r = reinterpret_cast<const float2*>(W1 + (size_t)(d0 + j) * U);
#pragma unroll
            for (int k = 0; k < 5; k++) {
                float2 v = r[k];
                tmp[j][2 * k] = v.x; tmp[j][2 * k + 1] = v.y;
            }
        }
#pragma unroll
        for (int u = 0; u < U; u++)
#pragma unroll
            for (int j = 0; j < 4; j++) ws[u][d0 + j] = tmp[j][u];

        float4 s4 = *reinterpret_cast<const float4*>(sp + (size_t)b * S + d0);
        float sj[4] = {s4.x, s4.y, s4.z, s4.w};
        float p[U];
#pragma unroll
        for (int u = 0; u < U; u++) p[u] = 0.0f;
#pragma unroll
        for (int j = 0; j < 4; j++) {
            const float2* r = reinterpret_cast<const float2*>(W1 + (size_t)(D + d0 + j) * U);
#pragma unroll
            for (int k = 0; k < 5; k++) {
                float2 v = r[k];
                p[2 * k]     += sj[j] * v.x;
                p[2 * k + 1] += sj[j] * v.y;
            }
        }
#pragma unroll
        for (int off = 16; off; off >>= 1)
#pragma unroll
            for (int u = 0; u < U; u++) p[u] += __shfl_xor_sync(0xffffffffu, p[u], off);
        if (lane == 0) {
#pragma unroll
            for (int u = 0; u < U; u++) red[w][u] = p[u];
        }
    }

    // warp base for its d-half; warm group 0 lines in L2 (per-lane own addresses)
    const int tbase = ch * CT + pair * 8;
    const float* awp = a + ((size_t)(b * T + tbase)) * D + side * 512 + lane * 4;
#pragma unroll
    for (int g = 0; g < 4; g++) pf_l2(awp + (size_t)g * D);

    __syncthreads();
    if (tid < U) {
        float s = 0.0f;
#pragma unroll
        for (int k = 0; k < 8; k++) s += red[k][tid];
        u2s[tid] = s + b1[tid];
        w2s[tid] = W2v[tid];
    }
    if (tid == 0) b2s = b2[0];
    __syncthreads();

    // ---- main: 2 groups of 4 t per pair; one named barrier per group ----
    ull c01[4] = {0ull, 0ull, 0ull, 0ull}, c23[4] = {0ull, 0ull, 0ull, 0ull};

    for (int grp = 0; grp < 2; grp++) {
        const float* at0 = awp + (size_t)(grp * 4) * D;

        if (grp == 0) {                // warm next group's lines (per-lane addresses)
#pragma unroll
            for (int g = 4; g < 8; g++) pf_l2(awp + (size_t)g * D);
        }

        // packed accumulators: acc[p][u] holds (t(2p), t(2p+1)); u2 seeded once
        ull acc[2][U];
#pragma unroll
        for (int u = 0; u < U; u++) {
            float seed = (side == 0 && lane == 0) ? u2s[u] : 0.0f;
            ull sd = pack2(seed, seed);
            acc[0][u] = sd;
            acc[1][u] = (side == 0 && lane == 0) ? 0ull : 0ull;   // u2 only once per t!
        }
        // NOTE: u2 must be added once per (t,u); acc[0] covers t0,t1 and acc[1] t2,t3,
        // so BOTH need the seed:
#pragma unroll
        for (int u = 0; u < U; u++) {
            if (side == 0 && lane == 0) acc[1][u] = pack2(u2s[u], u2s[u]);
        }

#pragma unroll
        for (int p = 0; p < 4; p++) {
            const float* ap = at0 + p * 128;
            float4 av0 = *reinterpret_cast<const float4*>(ap);
            float4 av1 = *reinterpret_cast<const float4*>(ap + D);
            float4 av2 = *reinterpret_cast<const float4*>(ap + 2 * D);
            float4 av3 = *reinterpret_cast<const float4*>(ap + 3 * D);

            // cross-t packs: pair0 = (t0,t1), pair1 = (t2,t3), per d
            ull A0x = pack2(av0.x, av1.x), A0y = pack2(av0.y, av1.y);
            ull A0z = pack2(av0.z, av1.z), A0w = pack2(av0.w, av1.w);
            ull A1x = pack2(av2.x, av3.x), A1y = pack2(av2.y, av3.y);
            ull A1z = pack2(av2.z, av3.z), A1w = pack2(av2.w, av3.w);

            const int wb = side * 512 + p * 128 + lane * 4;
#pragma unroll
            for (int u = 0; u < U; u++) {
                float4 wq = *reinterpret_cast<const float4*>(&ws[u][wb]);
                ull wx = pack2(wq.x, wq.x), wy = pack2(wq.y, wq.y);
                ull wz = pack2(wq.z, wq.z), ww = pack2(wq.w, wq.w);
                acc[0][u] = fma2(A0x, wx, fma2(A0y, wy, fma2(A0z, wz, fma2(A0w, ww, acc[0][u]))));
                acc[1][u] = fma2(A1x, wx, fma2(A1y, wy, fma2(A1z, wz, fma2(A1w, ww, acc[1][u]))));
            }
        }

        // unpack to 40 floats, then 32-lane butterfly (40 interleaved chains)
        float s0[U], s1[U], s2[U], s3[U];
#pragma unroll
        for (int u = 0; u < U; u++) {
            float2 f = unpack2(acc[0][u]); s0[u] = f.x; s1[u] = f.y;
            f = unpack2(acc[1][u]);        s2[u] = f.x; s3[u] = f.y;
        }
#pragma unroll
        for (int off = 16; off; off >>= 1)
#pragma unroll
            for (int u = 0; u < U; u++) {
                s0[u] += __shfl_xor_sync(0xffffffffu, s0[u], off);
                s1[u] += __shfl_xor_sync(0xffffffffu, s1[u], off);
                s2[u] += __shfl_xor_sync(0xffffffffu, s2[u], off);
                s3[u] += __shfl_xor_sync(0xffffffffu, s3[u], off);
            }

        // exchange halves within pair (double-buffered by group parity)
        float* pb = &pairbuf[grp & 1][pair][side][0];
        if (lane == 0) {
            float4* pv = reinterpret_cast<float4*>(pb);
            pv[0] = make_float4(s0[0], s0[1], s0[2], s0[3]);
            pv[1] = make_float4(s0[4], s0[5], s0[6], s0[7]);
            pv[2] = make_float4(s0[8], s0[9], s1[0], s1[1]);
            pv[3] = make_float4(s1[2], s1[3], s1[4], s1[5]);
            pv[4] = make_float4(s1[6], s1[7], s1[8], s1[9]);
            pv[5] = make_float4(s2[0], s2[1], s2[2], s2[3]);
            pv[6] = make_float4(s2[4], s2[5], s2[6], s2[7]);
            pv[7] = make_float4(s2[8], s2[9], s3[0], s3[1]);
            pv[8] = make_float4(s3[2], s3[3], s3[4], s3[5]);
            pv[9] = make_float4(s3[6], s3[7], s3[8], s3[9]);
        }
        asm volatile("bar.sync %0, 64;" :: "r"(1 + pair) : "memory");
        const float* po = &pairbuf[grp & 1][pair][side ^ 1][0];

        // e -> relu -> exp (both warps redundantly; max-free since e in [0,~3])
        float e0 = b2s, e1 = b2s, e2 = b2s, e3 = b2s;
#pragma unroll
        for (int u = 0; u < U; u++) {
            e0 += w2s[u] * fast_tanh(s0[u] + po[u]);
            e1 += w2s[u] * fast_tanh(s1[u] + po[10 + u]);
            e2 += w2s[u] * fast_tanh(s2[u] + po[20 + u]);
            e3 += w2s[u] * fast_tanh(s3[u] + po[30 + u]);
        }
        float ex0 = __expf(fmaxf(e0, 0.0f));
        float ex1 = __expf(fmaxf(e1, 0.0f));
        float ex2 = __expf(fmaxf(e2, 0.0f));
        float ex3 = __expf(fmaxf(e3, 0.0f));
        if (side == 0 && lane == 0)
            *reinterpret_cast<float4*>(&g_e[b * T + tbase + grp * 4]) =
                make_float4(ex0, ex1, ex2, ex3);

        // context accumulation: reread group window (L1-hot)
        ull E0 = pack2(ex0, ex0), E1 = pack2(ex1, ex1);
        ull E2 = pack2(ex2, ex2), E3 = pack2(ex3, ex3);
#pragma unroll
        for (int p = 0; p < 4; p++) {
            const float* ap = at0 + p * 128;
            float4 r0 = *reinterpret_cast<const float4*>(ap);
            float4 r1 = *reinterpret_cast<const float4*>(ap + D);
            float4 r2 = *reinterpret_cast<const float4*>(ap + 2 * D);
            float4 r3 = *reinterpret_cast<const float4*>(ap + 3 * D);
            c01[p] = fma2(E0, pack2(r0.x, r0.y), c01[p]);
            c23[p] = fma2(E0, pack2(r0.z, r0.w), c23[p]);
            c01[p] = fma2(E1, pack2(r1.x, r1.y), c01[p]);
            c23[p] = fma2(E1, pack2(r1.z, r1.w), c23[p]);
            c01[p] = fma2(E2, pack2(r2.x, r2.y), c01[p]);
            c23[p] = fma2(E2, pack2(r2.z, r2.w), c23[p]);
            c01[p] = fma2(E3, pack2(r3.x, r3.y), c01[p]);
            c23[p] = fma2(E3, pack2(r3.z, r3.w), c23[p]);
        }
    }

    // ---- block-level ctx combine (reuse ws smem), one global write per d ----
    __syncthreads();
    float* cbuf = &ws[0][0];                 // 4 pairs x 1024 d = 16 KB
#pragma unroll
    for (int p = 0; p < 4; p++) {
        float2 lo = unpack2(c01[p]), hi = unpack2(c23[p]);
        *reinterpret_cast<float4*>(&cbuf[pair * D + side * 512 + p * 128 + lane * 4]) =
            make_float4(lo.x, lo.y, hi.x, hi.y);
    }
    __syncthreads();
    {
        const int d0 = 4 * tid;
        float4 cs = make_float4(0.f, 0.f, 0.f, 0.f);
#pragma unroll
        for (int q = 0; q < 4; q++) {
            float4 v = *reinterpret_cast<const float4*>(&cbuf[q * D + d0]);
            cs.x += v.x; cs.y += v.y; cs.z += v.z; cs.w += v.w;
        }
        *reinterpret_cast<float4*>(&g_cpart[((size_t)(b * NCHK + ch)) * D + d0]) = cs;
    }
}

// ---------- K2: combine 16 chunk partials, normalize, write outputs ----------
// 256 blocks: 4 d-quarters per batch; z computed redundantly per block.
__global__ void k2_combine(float* __restrict__ out, int scoreOff, int doScores) {
    int bq = blockIdx.x;
    int b = bq >> 2, dq = bq & 3;
    int tid = threadIdx.x;
    __shared__ float redz[8];
    __shared__ float zsh;

    float e0 = g_e[b * T + tid];
    float e1 = g_e[b * T + 256 + tid];
    float s = e0 + e1;
#pragma unroll
    for (int off = 16; off; off >>= 1) s += __shfl_xor_sync(0xffffffffu, s, off);
    if ((tid & 31) == 0) redz[tid >> 5] = s;
    __syncthreads();
    if (tid == 0) {
        float z = 0.0f;
#pragma unroll
        for (int k = 0; k < 8; k++) z += redz[k];
        zsh = 1.0f / z;              // z >= 512 (e >= 0), safe
    }
    __syncthreads();
    float invZ = zsh;

    if (dq == 0 && doScores) {
        out[scoreOff + b * T + tid]       = e0 * invZ;
        out[scoreOff + b * T + 256 + tid] = e1 * invZ;
    }

    int d = dq * 256 + tid;
    float c = 0.0f;
#pragma unroll
    for (int chn = 0; chn < NCHK; chn++)
        c += g_cpart[((size_t)(b * NCHK + chn)) * D + d];
    out[(size_t)b * D + d] = c * invZ;
}

extern "C" void kernel_launch(void* const* d_in, const int* in_sizes, int n_in,
                              void* d_out, int out_size) {
    const float* a   = (const float*)d_in[0];   // [B,T,D]
    const float* sp  = (const float*)d_in[1];   // [B,S]
    const float* W1  = (const float*)d_in[2];   // [D+S, 10]
    const float* b1  = (const float*)d_in[3];   // [10]
    const float* W2  = (const float*)d_in[4];   // [10, 1]
    const float* b2  = (const float*)d_in[5];   // [1]
    float* out = (float*)d_out;

    int scoreOff = B * D;
    int doScores = (out_size >= B * D + B * T) ? 1 : 0;

    k1_main<<<dim3(NCHK, B), 256>>>(a, sp, W1, W2, b1, b2);
    k2_combine<<<4 * B, 256>>>(out, scoreOff, doScores);
}